// round 6
// baseline (speedup 1.0000x reference)
#include <cuda_runtime.h>
#include <cuda_fp16.h>
#include <cstdint>

// Shapes (fixed by the problem)
#define B_ 64
#define S_ 197
#define D_ 768
#define P_ 196
#define M_ (B_ * S_)   // 12608 = 64 * 197

// Device scratch (no cudaMalloc allowed)
__device__ __half g_xs[(size_t)M_ * D_];    // weighted-gathered x, fp16
__device__ __half g_wt[(size_t)D_ * D_];    // Wv^T in fp16: g_wt[n][k]
__device__ float  g_ws[M_];                 // per-row weight sum

__device__ __forceinline__ uint32_t smem_u32(const void* p) {
    uint32_t a;
    asm("{ .reg .u64 t; cvta.to.shared.u64 t, %1; cvt.u32.u64 %0, t; }"
        : "=r"(a) : "l"(p));
    return a;
}
__device__ __forceinline__ void cp_async16(uint32_t dst, const void* src) {
    asm volatile("cp.async.cg.shared.global [%0], [%1], 16;"
                 :: "r"(dst), "l"(src));
}
#define CP_COMMIT() asm volatile("cp.async.commit_group;" ::: "memory")
#define CP_WAIT(n)  asm volatile("cp.async.wait_group %0;" :: "n"(n) : "memory")

__device__ __forceinline__ void mma_f16(float* d, const uint32_t* a, const uint32_t* b)
{
    asm volatile(
        "mma.sync.aligned.m16n8k16.row.col.f32.f16.f16.f32 "
        "{%0,%1,%2,%3}, {%4,%5,%6,%7}, {%8,%9}, {%0,%1,%2,%3};"
        : "+f"(d[0]), "+f"(d[1]), "+f"(d[2]), "+f"(d[3])
        : "r"(a[0]), "r"(a[1]), "r"(a[2]), "r"(a[3]), "r"(b[0]), "r"(b[1]));
}

// ---------------------------------------------------------------------------
// Fused prep: blocks [0, M_) do the weighted gather of x -> xs (fp16) + wsum;
// blocks [M_, M_+576) transpose+convert Wv -> Wt[n][k] fp16.
// ---------------------------------------------------------------------------
__device__ __forceinline__ int wrap197(int i)
{
    int r = i % S_;
    return (r < 0) ? r + S_ : r;
}

__global__ __launch_bounds__(192) void prep_kernel(
    const float* __restrict__ x, const int* __restrict__ img_ids,
    const float* __restrict__ avgs, const float* __restrict__ stds,
    const float* __restrict__ noise, const float* __restrict__ W,
    __half* __restrict__ xs, __half* __restrict__ wt, float* __restrict__ wsum)
{
    __shared__ float tile[32][33];
    const int bid = blockIdx.x;
    const int tid = threadIdx.x;

    if (bid >= M_) {
        // ---- transpose tile ----
        const int t  = bid - M_;        // 0..575
        const int tx = t % 24;          // col tile of W
        const int ty = t / 24;          // row tile of W
        const int lx = tid & 31;        // 0..31
        const int ly = tid >> 5;        // 0..5
#pragma unroll
        for (int i = 0; i < 36; i += 6) {
            const int r = ly + i;
            if (r < 32)
                tile[r][lx] = W[(size_t)(ty * 32 + r) * D_ + tx * 32 + lx];
        }
        __syncthreads();
#pragma unroll
        for (int i = 0; i < 36; i += 6) {
            const int r = ly + i;
            if (r < 32)
                wt[(size_t)(tx * 32 + r) * D_ + ty * 32 + lx] =
                    __float2half_rn(tile[lx][r]);
        }
        return;
    }

    // ---- gather row ----
    const int row = bid;
    const int b = row / S_;
    const int s = row - b * S_;
    const int t = tid;                  // 0..191, 4 elements each

    uint2* orow = (uint2*)(xs + (size_t)row * D_) + t;
    if (s == 0) {
        *orow = make_uint2(0u, 0u);
        if (t == 0) wsum[row] = 0.0f;
        return;
    }
    const int p = s - 1;
    const int id = img_ids[b];
    const float nx = noise[(size_t)(b * 2 + 0) * P_ + p];
    const float ny = noise[(size_t)(b * 2 + 1) * P_ + p];
    const size_t gb = (size_t)id * 2 * P_;
    const float ax = avgs[gb + p],  ay = avgs[gb + P_ + p];
    const float sx = stds[gb + p],  sy = stds[gb + P_ + p];

    const float kx = (nx - ax) / sx;
    const float ky = (ny - ay) / sy;
    const float x1 = ceilf(kx),  x2 = floorf(kx);
    const float y1 = ceilf(ky),  y2 = floorf(ky);
    const float wx1 = 1.0f - fabsf(x1 - kx);
    const float wx2 = 1.0f - fabsf(x2 - kx);
    const float wy1 = 1.0f - fabsf(y1 - ky);
    const float wy2 = 1.0f - fabsf(y2 - ky);
    const float w11 = wx1 * wy1, w21 = wx2 * wy1;
    const float w12 = wx1 * wy2, w22 = wx2 * wy2;

    const int i11 = wrap197((int)(14.0f * y1 + x1));
    const int i21 = wrap197((int)(14.0f * y1 + x2));
    const int i12 = wrap197((int)(14.0f * y2 + x1));
    const int i22 = wrap197((int)(14.0f * y2 + x2));

    const float4* xb = (const float4*)x + (size_t)b * S_ * (D_ / 4);
    const float4 a = xb[(size_t)i11 * (D_ / 4) + t];
    const float4 c = xb[(size_t)i21 * (D_ / 4) + t];
    const float4 d = xb[(size_t)i12 * (D_ / 4) + t];
    const float4 e = xb[(size_t)i22 * (D_ / 4) + t];

    float4 r;
    r.x = w11 * a.x + w21 * c.x + w12 * d.x + w22 * e.x;
    r.y = w11 * a.y + w21 * c.y + w12 * d.y + w22 * e.y;
    r.z = w11 * a.z + w21 * c.z + w12 * d.z + w22 * e.z;
    r.w = w11 * a.w + w21 * c.w + w12 * d.w + w22 * e.w;

    __half2 h0 = __floats2half2_rn(r.x, r.y);
    __half2 h1 = __floats2half2_rn(r.z, r.w);
    uint2 o;
    o.x = *(uint32_t*)&h0;
    o.y = *(uint32_t*)&h1;
    *orow = o;

    if (t == 0) wsum[row] = w11 + w21 + w12 + w22;
}

// ---------------------------------------------------------------------------
// FP16 tensor GEMM: out[M_,768] = xs @ Wt^T + wsum*bias (cls rows = 1.0)
// CTA 64x128 (197 x 6 grid, EXACT: no bounds checks), BK=32, 4-stage
// cp.async with ONE barrier per stage, 8 warps (2m x 4n), 32x32 warp tiles.
// 80B row pitch -> conflict-free fragment LDS. 3 CTAs/SM.
// ---------------------------------------------------------------------------
#define BK     32
#define NSTG   24          // 768/32
#define STAGES 4
#define ROWB   80          // bytes per smem row (64 data + 16 pad)
#define A_TILE (64 * ROWB)             // 5120
#define B_TILE (128 * ROWB)            // 10240
#define STAGE_B (A_TILE + B_TILE)      // 15360
#define SMEM_TOTAL (STAGES * STAGE_B)  // 61440

__global__ __launch_bounds__(256, 3) void gemm_f16(
    const __half* __restrict__ A, const __half* __restrict__ Bt,
    const float* __restrict__ bias, const float* __restrict__ wsum,
    float* __restrict__ C)
{
    extern __shared__ char smem[];
    const uint32_t sb = smem_u32(smem);

    const int tid  = threadIdx.x;
    const int wid  = tid >> 5;
    const int lane = tid & 31;
    const int g    = lane >> 2;       // 0..7
    const int t4   = lane & 3;        // 0..3
    const int wm   = wid & 1;         // 2 warp rows -> 32 m each
    const int wn   = wid >> 1;        // 4 warp cols -> 32 n each
    const int m0 = blockIdx.y * 64;
    const int n0 = blockIdx.x * 128;

    // cp.async maps: A = 256 chunks (1/thread), B = 512 chunks (2/thread)
    const int ar = tid >> 2,  ac = tid & 3;
    const int br0 = tid >> 2, bc0 = tid & 3;
    const int br1 = (tid + 256) >> 2, bc1 = (tid + 256) & 3;

    const __half* Ap  = A  + (size_t)(m0 + ar) * D_ + ac * 8;
    const __half* Bp0 = Bt + (size_t)(n0 + br0) * D_ + bc0 * 8;
    const __half* Bp1 = Bt + (size_t)(n0 + br1) * D_ + bc1 * 8;

    const uint32_t aDst  = sb + (uint32_t)(ar * ROWB + ac * 16);
    const uint32_t bDst0 = sb + A_TILE + (uint32_t)(br0 * ROWB + bc0 * 16);
    const uint32_t bDst1 = sb + A_TILE + (uint32_t)(br1 * ROWB + bc1 * 16);

    float acc[2][4][4];
#pragma unroll
    for (int i = 0; i < 2; i++)
#pragma unroll
        for (int j = 0; j < 4; j++)
#pragma unroll
            for (int r = 0; r < 4; r++) acc[i][j][r] = 0.0f;

    // prologue: issue stages 0..STAGES-2
#pragma unroll
    for (int s = 0; s < STAGES - 1; s++) {
        const int k0 = s * BK;
        const uint32_t so = (uint32_t)(s * STAGE_B);
        cp_async16(aDst + so,  Ap  + k0);
        cp_async16(bDst0 + so, Bp0 + k0);
        cp_async16(bDst1 + so, Bp1 + k0);
        CP_COMMIT();
    }

    for (int s = 0; s < NSTG; s++) {
        CP_WAIT(STAGES - 2);          // own stage-s group complete
        __syncthreads();              // everyone's stage-s data visible;
                                      // all warps done reading slot (s-1)%4
        const int sl = s + STAGES - 1;
        if (sl < NSTG) {
            const int k0 = sl * BK;
            const uint32_t so = (uint32_t)((sl & (STAGES - 1)) * STAGE_B);
            cp_async16(aDst + so,  Ap  + k0);
            cp_async16(bDst0 + so, Bp0 + k0);
            cp_async16(bDst1 + so, Bp1 + k0);
        }
        CP_COMMIT();                  // empty group in tail keeps count right

        const char* Ab = smem + (s & (STAGES - 1)) * STAGE_B;
        const char* Bb = Ab + A_TILE;
#pragma unroll
        for (int kk = 0; kk < 2; kk++) {            // two k16 steps in BK=32
            const int kb = kk * 32 + t4 * 4;
            uint32_t a[2][4], b[4][2];
#pragma unroll
            for (int fm = 0; fm < 2; fm++) {
                const char* p0 = Ab + (wm * 32 + fm * 16 + g) * ROWB + kb;
                const char* p1 = p0 + 8 * ROWB;
                a[fm][0] = *(const uint32_t*)(p0);
                a[fm][1] = *(const uint32_t*)(p1);
                a[fm][2] = *(const uint32_t*)(p0 + 16);
                a[fm][3] = *(const uint32_t*)(p1 + 16);
            }
#pragma unroll
            for (int fn = 0; fn < 4; fn++) {
                const char* p = Bb + (wn * 32 + fn * 8 + g) * ROWB + kb;
                b[fn][0] = *(const uint32_t*)(p);
                b[fn][1] = *(const uint32_t*)(p + 16);
            }
#pragma unroll
            for (int fm = 0; fm < 2; fm++)
#pragma unroll
                for (int fn = 0; fn < 4; fn++)
                    mma_f16(acc[fm][fn], a[fm], b[fn]);
        }
    }

    // epilogue: out = acc + wsum[row]*bias[col]; class-token rows = 1.0
#pragma unroll
    for (int fm = 0; fm < 2; fm++) {
        const int row0 = m0 + wm * 32 + fm * 16 + g;
        const int row1 = row0 + 8;
        const bool cls0 = (row0 % S_) == 0;
        const bool cls1 = (row1 % S_) == 0;
        const float ws0 = wsum[row0];
        const float ws1 = wsum[row1];
#pragma unroll
        for (int fn = 0; fn < 4; fn++) {
            const int col = n0 + wn * 32 + fn * 8 + t4 * 2;
            const float b0 = bias[col];
            const float b1 = bias[col + 1];
            float2 o0, o1;
            o0.x = cls0 ? 1.0f : acc[fm][fn][0] + ws0 * b0;
            o0.y = cls0 ? 1.0f : acc[fm][fn][1] + ws0 * b1;
            o1.x = cls1 ? 1.0f : acc[fm][fn][2] + ws1 * b0;
            o1.y = cls1 ? 1.0f : acc[fm][fn][3] + ws1 * b1;
            *(float2*)(C + (size_t)row0 * D_ + col) = o0;
            *(float2*)(C + (size_t)row1 * D_ + col) = o1;
        }
    }
}

// ---------------------------------------------------------------------------
// Inputs (metadata order): 0:x 1:img_ids 2:mask 3:Wq 4:bq 5:Wk 6:bk
//                          7:Wv 8:bv 9:avgs 10:std_devs 11:noise
// q/k/softmax are dead (softmax over singleton axis == 1): out = sampled v,
// and sampling commutes with the linear map -> gather x first, then one GEMM.
// ---------------------------------------------------------------------------
extern "C" void kernel_launch(void* const* d_in, const int* in_sizes, int n_in,
                              void* d_out, int out_size)
{
    const float* x       = (const float*)d_in[0];
    const int*   img_ids = (const int*)d_in[1];
    const float* Wv      = (const float*)d_in[7];
    const float* bv      = (const float*)d_in[8];
    const float* avgs    = (const float*)d_in[9];
    const float* stds    = (const float*)d_in[10];
    const float* noise   = (const float*)d_in[11];
    float* out = (float*)d_out;

    __half* xs = nullptr;
    __half* wt = nullptr;
    float*  ws = nullptr;
    cudaGetSymbolAddress((void**)&xs, g_xs);
    cudaGetSymbolAddress((void**)&wt, g_wt);
    cudaGetSymbolAddress((void**)&ws, g_ws);

    cudaFuncSetAttribute(gemm_f16, cudaFuncAttributeMaxDynamicSharedMemorySize,
                         SMEM_TOTAL);

    prep_kernel<<<M_ + 576, 192>>>(x, img_ids, avgs, stds, noise, Wv, xs, wt, ws);
    gemm_f16<<<dim3(6, 197), 256, SMEM_TOTAL>>>(xs, wt, bv, ws, out);
}